// round 2
// baseline (speedup 1.0000x reference)
#include <cuda_runtime.h>
#include <cuda_bf16.h>
#include <math.h>
#include <stdint.h>

#define BB   128
#define SSQ  512
#define EE   300
#define HH   256
#define FH   1024
#define TT   9
#define MTOT (BB*SSQ)

// ---------------- static device scratch ----------------
__device__ float g_gA[(size_t)MTOT * FH];
__device__ float g_gB[(size_t)MTOT * FH];
__device__ float g_l0[(size_t)MTOT * 2 * HH];
__device__ float g_l1[(size_t)MTOT * 2 * HH];
__device__ float g_h[2][2][HH * BB];
__device__ float g_em[(size_t)MTOT * TT];
__device__ float g_part[BB];
__device__ unsigned g_cnt[2];
__device__ unsigned g_gen[2];

// ---------------- SGEMM: C[M,N] = A@W^T + bias ----------------
__global__ void __launch_bounds__(256)
sgemm_bias_kernel(const float* __restrict__ A, const float* __restrict__ W,
                  const float* __restrict__ bias, float* __restrict__ C,
                  int M, int N, int K,
                  const int* __restrict__ rowidx, int rowlen)
{
    __shared__ float As[2][8][128];
    __shared__ float Bs[2][8][128];
    __shared__ int   xrow[128];

    const int tid = threadIdx.x;
    const int m0 = blockIdx.x * 128;
    const int n0 = blockIdx.y * 128;

    if (rowidx && tid < 128) xrow[tid] = rowidx[m0 + tid];
    __syncthreads();

    const int lr = tid >> 1;
    const int lk = (tid & 1) * 4;

    const float* arow;
    if (rowidx) arow = A + (size_t)xrow[lr] * rowlen;
    else        arow = A + (size_t)(m0 + lr) * rowlen;
    const float* wrow = W + (size_t)(n0 + lr) * K;

    const int tm = tid >> 4;
    const int tn = tid & 15;

    float acc[8][8];
#pragma unroll
    for (int i = 0; i < 8; i++)
#pragma unroll
        for (int j = 0; j < 8; j++) acc[i][j] = 0.f;

    const int nkt = (K + 7) / 8;
    {
        int k = lk;
        float4 a4 = make_float4(0,0,0,0), b4 = make_float4(0,0,0,0);
        if (k < K) { a4 = *(const float4*)(arow + k); b4 = *(const float4*)(wrow + k); }
        As[0][lk+0][lr]=a4.x; As[0][lk+1][lr]=a4.y; As[0][lk+2][lr]=a4.z; As[0][lk+3][lr]=a4.w;
        Bs[0][lk+0][lr]=b4.x; Bs[0][lk+1][lr]=b4.y; Bs[0][lk+2][lr]=b4.z; Bs[0][lk+3][lr]=b4.w;
    }
    __syncthreads();

    for (int kt = 0; kt < nkt; kt++) {
        const int buf = kt & 1;
        float4 a4n = make_float4(0,0,0,0), b4n = make_float4(0,0,0,0);
        const bool more = (kt + 1 < nkt);
        if (more) {
            int k = (kt + 1) * 8 + lk;
            if (k < K) { a4n = *(const float4*)(arow + k); b4n = *(const float4*)(wrow + k); }
        }
#pragma unroll
        for (int kk = 0; kk < 8; kk++) {
            float4 a0 = *(const float4*)&As[buf][kk][tm*4];
            float4 a1 = *(const float4*)&As[buf][kk][64 + tm*4];
            float4 b0 = *(const float4*)&Bs[buf][kk][tn*4];
            float4 b1 = *(const float4*)&Bs[buf][kk][64 + tn*4];
            float av[8], bv[8];
            av[0]=a0.x; av[1]=a0.y; av[2]=a0.z; av[3]=a0.w;
            av[4]=a1.x; av[5]=a1.y; av[6]=a1.z; av[7]=a1.w;
            bv[0]=b0.x; bv[1]=b0.y; bv[2]=b0.z; bv[3]=b0.w;
            bv[4]=b1.x; bv[5]=b1.y; bv[6]=b1.z; bv[7]=b1.w;
#pragma unroll
            for (int i = 0; i < 8; i++)
#pragma unroll
                for (int j = 0; j < 8; j++) acc[i][j] += av[i] * bv[j];
        }
        if (more) {
            const int nb = buf ^ 1;
            As[nb][lk+0][lr]=a4n.x; As[nb][lk+1][lr]=a4n.y; As[nb][lk+2][lr]=a4n.z; As[nb][lk+3][lr]=a4n.w;
            Bs[nb][lk+0][lr]=b4n.x; Bs[nb][lk+1][lr]=b4n.y; Bs[nb][lk+2][lr]=b4n.z; Bs[nb][lk+3][lr]=b4n.w;
        }
        __syncthreads();
    }

    float4 bias0 = *(const float4*)(bias + n0 + tn*4);
    float4 bias1 = *(const float4*)(bias + n0 + 64 + tn*4);
    float bb0[4] = {bias0.x, bias0.y, bias0.z, bias0.w};
    float bb1[4] = {bias1.x, bias1.y, bias1.z, bias1.w};

#pragma unroll
    for (int hm = 0; hm < 2; hm++) {
#pragma unroll
        for (int i = 0; i < 4; i++) {
            const int ai = hm*4 + i;
            const int m  = m0 + hm*64 + tm*4 + i;
            float* crow = C + (size_t)m * N + n0;
            float4 o0, o1;
            o0.x = acc[ai][0] + bb0[0]; o0.y = acc[ai][1] + bb0[1];
            o0.z = acc[ai][2] + bb0[2]; o0.w = acc[ai][3] + bb0[3];
            o1.x = acc[ai][4] + bb1[0]; o1.y = acc[ai][5] + bb1[1];
            o1.z = acc[ai][6] + bb1[2]; o1.w = acc[ai][7] + bb1[3];
            *(float4*)(crow + tn*4)      = o0;
            *(float4*)(crow + 64 + tn*4) = o1;
        }
    }
}

// ---------------- LSTM scan ----------------
#define SCAN_SMEM_FLOATS (32768 + 4096 + 2048 + 2048 + 512 + 2048)
#define SCAN_SMEM_BYTES  (SCAN_SMEM_FLOATS * 4)

__device__ __forceinline__ float sigm(float x) { return 1.0f / (1.0f + expf(-x)); }

__global__ void __launch_bounds__(256, 1)
lstm_scan_kernel(const float* __restrict__ xWf, const float* __restrict__ xWb,
                 const float* __restrict__ WhhF, const float* __restrict__ WhhB,
                 float* __restrict__ lout)
{
    extern __shared__ float smem[];
    float* hs  = smem;            // [256][128]
    float* ws  = hs  + 32768;     // [16][256]
    float* gst = ws  + 4096;      // [16][128]
    float* xst = gst + 2048;      // [16][128]
    float* cst = xst + 2048;      // [4][128]
    float* pst = cst + 512;       // [128][16]

    const int tid   = threadIdx.x;
    const int dir   = blockIdx.x >> 6;
    const int slice = blockIdx.x & 63;
    const int j0    = slice << 2;

    const float* xW  = dir ? xWb  : xWf;
    const float* Whh = dir ? WhhB : WhhF;

    {
        const int l  = tid >> 4;
        const int ks = (tid & 15) * 16;
        const int grow = ((l >> 2) * HH) + j0 + (l & 3);
#pragma unroll
        for (int i = 0; i < 16; i += 4)
            *(float4*)&ws[l*256 + ks + i] = *(const float4*)&Whh[(size_t)grow*HH + ks + i];
    }
    {
        float4* d4 = (float4*)hs;
        float4 z = make_float4(0,0,0,0);
#pragma unroll
        for (int i = 0; i < 32; i++) d4[tid + (i << 8)] = z;
        if (tid < 128) { cst[tid] = 0.f; cst[128+tid] = 0.f; cst[256+tid] = 0.f; cst[384+tid] = 0.f; }
    }
    __syncthreads();

    for (int tt = 0; tt < SSQ; tt++) {
        const int t = dir ? (SSQ - 1 - tt) : tt;

        if (tt > 0) {
            const float4* s4 = (const float4*)(g_h[(tt - 1) & 1][dir]);
            float4* d4 = (float4*)hs;
#pragma unroll
            for (int i = 0; i < 32; i++) d4[tid + (i << 8)] = s4[tid + (i << 8)];
        }
#pragma unroll
        for (int half = 0; half < 2; half++) {
            const int p = tid + (half << 8);
            const int q = p >> 7;
            const int b = p & 127;
            float4 v = *(const float4*)&xW[((size_t)b * SSQ + t) * FH + (q << 8) + j0];
            xst[((q<<2)+0)*128 + b] = v.x;
            xst[((q<<2)+1)*128 + b] = v.y;
            xst[((q<<2)+2)*128 + b] = v.z;
            xst[((q<<2)+3)*128 + b] = v.w;
        }
        __syncthreads();

        {
            const int kh = tid >> 7;
            const int ts = tid & 127;
            const int rq = ts >> 5;
            const int bq = ts & 31;
            const int r0 = rq << 2;
            float acc[4][4];
#pragma unroll
            for (int i=0;i<4;i++)
#pragma unroll
                for (int j=0;j<4;j++) acc[i][j] = 0.f;

            const float4* hs4 = (const float4*)hs;
            const float4* ws4 = (const float4*)ws;
            const int kw = kh << 5;

#pragma unroll 4
            for (int k4 = 0; k4 < 32; k4++) {
                float w_[4][4];
#pragma unroll
                for (int i = 0; i < 4; i++) {
                    float4 tw = ws4[(r0+i)*64 + kw + k4];
                    w_[i][0]=tw.x; w_[i][1]=tw.y; w_[i][2]=tw.z; w_[i][3]=tw.w;
                }
                const int kb = (kh << 7) + (k4 << 2);
#pragma unroll
                for (int c = 0; c < 4; c++) {
                    float4 hh = hs4[(kb + c)*32 + bq];
#pragma unroll
                    for (int i = 0; i < 4; i++) {
                        const float wv = w_[i][c];
                        acc[i][0] += wv * hh.x;
                        acc[i][1] += wv * hh.y;
                        acc[i][2] += wv * hh.z;
                        acc[i][3] += wv * hh.w;
                    }
                }
            }
            if (kh) {
#pragma unroll
                for (int i=0;i<4;i++)
#pragma unroll
                    for (int j=0;j<4;j++) pst[ts*16 + i*4 + j] = acc[i][j];
            }
            __syncthreads();
            if (!kh) {
#pragma unroll
                for (int i=0;i<4;i++)
#pragma unroll
                    for (int j=0;j<4;j++)
                        gst[(r0+i)*128 + (bq<<2) + j] = acc[i][j] + pst[ts*16 + i*4 + j];
            }
            __syncthreads();
        }

        if (tid < 128) {
            const int b = tid;
            float* hdst = g_h[tt & 1][dir];
            float hj[4];
#pragma unroll
            for (int jj = 0; jj < 4; jj++) {
                float gi = gst[(0  + jj)*128 + b] + xst[(0  + jj)*128 + b];
                float gf = gst[(4  + jj)*128 + b] + xst[(4  + jj)*128 + b];
                float gg = gst[(8  + jj)*128 + b] + xst[(8  + jj)*128 + b];
                float go = gst[(12 + jj)*128 + b] + xst[(12 + jj)*128 + b];
                float c  = cst[jj*128 + b];
                float si = sigm(gi), sf = sigm(gf), so = sigm(go);
                c = sf * c + si * tanhf(gg);
                float h = so * tanhf(c);
                cst[jj*128 + b] = c;
                hdst[(j0 + jj)*128 + b] = h;
                hj[jj] = h;
            }
            *(float4*)&lout[((size_t)b * SSQ + t) * (2*HH) + dir*HH + j0] =
                make_float4(hj[0], hj[1], hj[2], hj[3]);
        }
        __threadfence();
        __syncthreads();

        if (tt < SSQ - 1) {
            if (tid == 0) {
                unsigned gen = *(volatile unsigned*)&g_gen[dir];
                if (atomicAdd(&g_cnt[dir], 1u) == 63u) {
                    atomicExch(&g_cnt[dir], 0u);
                    __threadfence();
                    atomicAdd(&g_gen[dir], 1u);
                } else {
                    while (*(volatile unsigned*)&g_gen[dir] == gen) __nanosleep(64);
                }
                __threadfence();
            }
            __syncthreads();
        }
    }
}

// ---------------- FC (T=9) ----------------
__global__ void __launch_bounds__(256)
fc_kernel(const float* __restrict__ l1, const float* __restrict__ fcw,
          const float* __restrict__ fcb, float* __restrict__ em)
{
    __shared__ float wsm[TT * 512];
    __shared__ float wb[TT];
    const int tid = threadIdx.x;
    for (int i = tid; i < TT*512; i += 256) wsm[i] = fcw[i];
    if (tid < TT) wb[tid] = fcb[tid];
    __syncthreads();

    const int warp = tid >> 5, lane = tid & 31;
    const int m = blockIdx.x * 8 + warp;
    const float* arow = l1 + (size_t)m * 512;
    float a[16];
#pragma unroll
    for (int c = 0; c < 16; c++) a[c] = arow[c*32 + lane];
    float* emrow = em + (size_t)m * TT;
#pragma unroll
    for (int j = 0; j < TT; j++) {
        float s = 0.f;
#pragma unroll
        for (int c = 0; c < 16; c++) s += a[c] * wsm[j*512 + c*32 + lane];
#pragma unroll
        for (int o = 16; o; o >>= 1) s += __shfl_xor_sync(0xffffffffu, s, o);
        if (lane == 0) emrow[j] = s + wb[j];
    }
}

// ---------------- CRF ----------------
__global__ void __launch_bounds__(1024)
crf_kernel(const int* __restrict__ x, const int* __restrict__ tags,
           const float* __restrict__ em, const float* __restrict__ start,
           const float* __restrict__ endv, const float* __restrict__ trans,
           float* __restrict__ partial)
{
    const int gw = (blockIdx.x * blockDim.x + threadIdx.x) >> 5;
    const int lane = threadIdx.x & 31;
    if (gw >= BB) return;
    const int b = gw;
    const float* emr = em + (size_t)b * SSQ * TT;
    const int* tg = tags + (size_t)b * SSQ;
    const int* xb = x + (size_t)b * SSQ;

    float nsum = 0.f; int mcount = 0;
    for (int s = lane; s < SSQ; s += 32) {
        const int m = (xb[s] != 0);
        mcount += m;
        if (s >= 1 && m) {
            const int tp = tg[s-1], tc = tg[s];
            nsum += trans[tp*TT + tc] + emr[(size_t)s*TT + tc];
        }
    }
#pragma unroll
    for (int o = 16; o; o >>= 1) {
        nsum   += __shfl_xor_sync(0xffffffffu, nsum, o);
        mcount += __shfl_xor_sync(0xffffffffu, mcount, o);
    }
    int last = mcount - 1; if (last < 0) last = 0;
    const int t0 = tg[0], tl = tg[last];
    const float num = nsum + start[t0] + emr[t0] + endv[tl];

    float tcol[TT];
#pragma unroll
    for (int i = 0; i < TT; i++) tcol[i] = 0.f;
    float alpha = -1e30f;
    if (lane < TT) {
#pragma unroll
        for (int i = 0; i < TT; i++) tcol[i] = trans[i*TT + lane];
        alpha = start[lane] + emr[lane];
    }
    for (int s = 1; s < SSQ; s++) {
        const float e = (lane < TT) ? emr[(size_t)s*TT + lane] : 0.f;
        const int m = (xb[s] != 0);
        float av[TT];
        float mx = -1e30f;
#pragma unroll
        for (int i = 0; i < TT; i++) {
            const float ai = __shfl_sync(0xffffffffu, alpha, i);
            av[i] = ai + tcol[i];
            mx = fmaxf(mx, av[i]);
        }
        float ssum = 0.f;
#pragma unroll
        for (int i = 0; i < TT; i++) ssum += expf(av[i] - mx);
        const float nxt = e + mx + logf(ssum);
        if (lane < TT && m) alpha = nxt;
    }
    float v = (lane < TT) ? alpha + endv[lane] : -1e30f;
    float mx = v;
#pragma unroll
    for (int o = 16; o; o >>= 1) mx = fmaxf(mx, __shfl_xor_sync(0xffffffffu, mx, o));
    float ex = (lane < TT) ? expf(v - mx) : 0.f;
#pragma unroll
    for (int o = 16; o; o >>= 1) ex += __shfl_xor_sync(0xffffffffu, ex, o);
    const float denom = mx + logf(ex);
    if (lane == 0) partial[b] = denom - num;
}

__global__ void reduce_mean_kernel(const float* __restrict__ partial, float* __restrict__ out)
{
    __shared__ float sm[BB];
    const int t = threadIdx.x;
    sm[t] = partial[t];
    __syncthreads();
    for (int o = 64; o; o >>= 1) { if (t < o) sm[t] += sm[t + o]; __syncthreads(); }
    if (t == 0) out[0] = sm[0] / (float)BB;
}

// ---------------- launch ----------------
extern "C" void kernel_launch(void* const* d_in, const int* in_sizes, int n_in,
                              void* d_out, int out_size)
{
    const int*   x     = (const int*)d_in[0];
    const int*   tags  = (const int*)d_in[1];
    const float* emb   = (const float*)d_in[2];
    const float* Wih0f = (const float*)d_in[3];
    const float* Whh0f = (const float*)d_in[4];
    const float* b0f   = (const float*)d_in[5];
    const float* Wih0b = (const float*)d_in[6];
    const float* Whh0b = (const float*)d_in[7];
    const float* b0b   = (const float*)d_in[8];
    const float* Wih1f = (const float*)d_in[9];
    const float* Whh1f = (const float*)d_in[10];
    const float* b1f   = (const float*)d_in[11];
    const float* Wih1b = (const float*)d_in[12];
    const float* Whh1b = (const float*)d_in[13];
    const float* b1b   = (const float*)d_in[14];
    const float* fcw   = (const float*)d_in[15];
    const float* fcb   = (const float*)d_in[16];
    const float* crf_s = (const float*)d_in[17];
    const float* crf_e = (const float*)d_in[18];
    const float* crf_t = (const float*)d_in[19];
    float* out = (float*)d_out;

    float *gA, *gB, *l0, *l1, *em, *part;
    cudaGetSymbolAddress((void**)&gA, g_gA);
    cudaGetSymbolAddress((void**)&gB, g_gB);
    cudaGetSymbolAddress((void**)&l0, g_l0);
    cudaGetSymbolAddress((void**)&l1, g_l1);
    cudaGetSymbolAddress((void**)&em, g_em);
    cudaGetSymbolAddress((void**)&part, g_part);

    cudaFuncSetAttribute(lstm_scan_kernel,
                         cudaFuncAttributeMaxDynamicSharedMemorySize, SCAN_SMEM_BYTES);

    dim3 gg(MTOT/128, FH/128);

    // layer 0 input projections (embedding gather fused)
    sgemm_bias_kernel<<<gg, 256>>>(emb, Wih0f, b0f, gA, MTOT, FH, EE, x, EE);
    sgemm_bias_kernel<<<gg, 256>>>(emb, Wih0b, b0b, gB, MTOT, FH, EE, x, EE);
    // layer 0 scan (both directions)
    lstm_scan_kernel<<<128, 256, SCAN_SMEM_BYTES>>>(gA, gB, Whh0f, Whh0b, l0);
    // layer 1 input projections
    sgemm_bias_kernel<<<gg, 256>>>(l0, Wih1f, b1f, gA, MTOT, FH, 2*HH, nullptr, 2*HH);
    sgemm_bias_kernel<<<gg, 256>>>(l0, Wih1b, b1b, gB, MTOT, FH, 2*HH, nullptr, 2*HH);
    // layer 1 scan
    lstm_scan_kernel<<<128, 256, SCAN_SMEM_BYTES>>>(gA, gB, Whh1f, Whh1b, l1);
    // emissions
    fc_kernel<<<MTOT/8, 256>>>(l1, fcw, fcb, em);
    // CRF NLL
    crf_kernel<<<4, 1024>>>(x, tags, em, crf_s, crf_e, crf_t, part);
    reduce_mean_kernel<<<1, 128>>>(part, out);
}

// round 3
// speedup vs baseline: 1.0547x; 1.0547x over previous
#include <cuda_runtime.h>
#include <cuda_bf16.h>
#include <math.h>
#include <stdint.h>

#define BB   128
#define SSQ  512
#define EE   300
#define HH   256
#define FH   1024
#define TT   9
#define MTOT (BB*SSQ)

// ---------------- static device scratch ----------------
__device__ float g_gA[(size_t)MTOT * FH];
__device__ float g_gB[(size_t)MTOT * FH];
__device__ float g_l0[(size_t)MTOT * 2 * HH];
__device__ float g_l1[(size_t)MTOT * 2 * HH];
__device__ float g_h[2][2][HH * BB];
__device__ float g_em[(size_t)MTOT * TT];
__device__ float g_part[BB];
__device__ unsigned g_cnt[2];
__device__ unsigned g_gen[2];

// ---------------- packed f32x2 helpers (Blackwell FFMA2) ----------------
__device__ __forceinline__ uint64_t pk2(float lo, float hi) {
    uint64_t r;
    asm("mov.b64 %0, {%1, %2};" : "=l"(r) : "f"(lo), "f"(hi));
    return r;
}
__device__ __forceinline__ void upk2(float& lo, float& hi, uint64_t v) {
    asm("mov.b64 {%0, %1}, %2;" : "=f"(lo), "=f"(hi) : "l"(v));
}
__device__ __forceinline__ void fma2(uint64_t& d, uint64_t a, uint64_t b) {
    asm("fma.rn.f32x2 %0, %1, %2, %0;" : "+l"(d) : "l"(a), "l"(b));
}

// ---------------- SGEMM: C[M,N] = A@W^T + bias (FFMA2 microkernel) ----------------
__global__ void __launch_bounds__(256)
sgemm_bias_kernel(const float* __restrict__ A, const float* __restrict__ W,
                  const float* __restrict__ bias, float* __restrict__ C,
                  int M, int N, int K,
                  const int* __restrict__ rowidx, int rowlen)
{
    __shared__ float As[2][8][128];
    __shared__ float Bs[2][8][128];
    __shared__ int   xrow[128];

    const int tid = threadIdx.x;
    const int m0 = blockIdx.x * 128;
    const int n0 = blockIdx.y * 128;

    if (rowidx && tid < 128) xrow[tid] = rowidx[m0 + tid];
    __syncthreads();

    const int lr = tid >> 1;
    const int lk = (tid & 1) * 4;

    const float* arow;
    if (rowidx) arow = A + (size_t)xrow[lr] * rowlen;
    else        arow = A + (size_t)(m0 + lr) * rowlen;
    const float* wrow = W + (size_t)(n0 + lr) * K;

    const int tm = tid >> 4;
    const int tn = tid & 15;

    // acc2[i][p] = packed pair of output columns (2p, 2p+1) within the 8-col microtile
    uint64_t acc2[8][4];
#pragma unroll
    for (int i = 0; i < 8; i++)
#pragma unroll
        for (int j = 0; j < 4; j++) acc2[i][j] = 0ull;

    const int nkt = (K + 7) / 8;
    {
        int k = lk;
        float4 a4 = make_float4(0,0,0,0), b4 = make_float4(0,0,0,0);
        if (k < K) { a4 = *(const float4*)(arow + k); b4 = *(const float4*)(wrow + k); }
        As[0][lk+0][lr]=a4.x; As[0][lk+1][lr]=a4.y; As[0][lk+2][lr]=a4.z; As[0][lk+3][lr]=a4.w;
        Bs[0][lk+0][lr]=b4.x; Bs[0][lk+1][lr]=b4.y; Bs[0][lk+2][lr]=b4.z; Bs[0][lk+3][lr]=b4.w;
    }
    __syncthreads();

    for (int kt = 0; kt < nkt; kt++) {
        const int buf = kt & 1;
        float4 a4n = make_float4(0,0,0,0), b4n = make_float4(0,0,0,0);
        const bool more = (kt + 1 < nkt);
        if (more) {
            int k = (kt + 1) * 8 + lk;
            if (k < K) { a4n = *(const float4*)(arow + k); b4n = *(const float4*)(wrow + k); }
        }
#pragma unroll
        for (int kk = 0; kk < 8; kk++) {
            float4 a0 = *(const float4*)&As[buf][kk][tm*4];
            float4 a1 = *(const float4*)&As[buf][kk][64 + tm*4];
            float4 b0 = *(const float4*)&Bs[buf][kk][tn*4];
            float4 b1 = *(const float4*)&Bs[buf][kk][64 + tn*4];
            uint64_t bp[4];
            bp[0] = pk2(b0.x, b0.y); bp[1] = pk2(b0.z, b0.w);
            bp[2] = pk2(b1.x, b1.y); bp[3] = pk2(b1.z, b1.w);
            float av[8];
            av[0]=a0.x; av[1]=a0.y; av[2]=a0.z; av[3]=a0.w;
            av[4]=a1.x; av[5]=a1.y; av[6]=a1.z; av[7]=a1.w;
#pragma unroll
            for (int i = 0; i < 8; i++) {
                const uint64_t ap = pk2(av[i], av[i]);
                fma2(acc2[i][0], ap, bp[0]);
                fma2(acc2[i][1], ap, bp[1]);
                fma2(acc2[i][2], ap, bp[2]);
                fma2(acc2[i][3], ap, bp[3]);
            }
        }
        if (more) {
            const int nb = buf ^ 1;
            As[nb][lk+0][lr]=a4n.x; As[nb][lk+1][lr]=a4n.y; As[nb][lk+2][lr]=a4n.z; As[nb][lk+3][lr]=a4n.w;
            Bs[nb][lk+0][lr]=b4n.x; Bs[nb][lk+1][lr]=b4n.y; Bs[nb][lk+2][lr]=b4n.z; Bs[nb][lk+3][lr]=b4n.w;
        }
        __syncthreads();
    }

    float4 bias0 = *(const float4*)(bias + n0 + tn*4);
    float4 bias1 = *(const float4*)(bias + n0 + 64 + tn*4);
    float bb0[4] = {bias0.x, bias0.y, bias0.z, bias0.w};
    float bb1[4] = {bias1.x, bias1.y, bias1.z, bias1.w};

#pragma unroll
    for (int hm = 0; hm < 2; hm++) {
#pragma unroll
        for (int i = 0; i < 4; i++) {
            const int ai = hm*4 + i;
            const int m  = m0 + hm*64 + tm*4 + i;
            float* crow = C + (size_t)m * N + n0;
            float v0,v1,v2,v3,v4,v5,v6,v7;
            upk2(v0, v1, acc2[ai][0]);
            upk2(v2, v3, acc2[ai][1]);
            upk2(v4, v5, acc2[ai][2]);
            upk2(v6, v7, acc2[ai][3]);
            float4 o0, o1;
            o0.x = v0 + bb0[0]; o0.y = v1 + bb0[1];
            o0.z = v2 + bb0[2]; o0.w = v3 + bb0[3];
            o1.x = v4 + bb1[0]; o1.y = v5 + bb1[1];
            o1.z = v6 + bb1[2]; o1.w = v7 + bb1[3];
            *(float4*)(crow + tn*4)      = o0;
            *(float4*)(crow + 64 + tn*4) = o1;
        }
    }
}

// ---------------- LSTM scan ----------------
#define SCAN_SMEM_FLOATS (32768 + 4096 + 2048 + 2048 + 512 + 2048)
#define SCAN_SMEM_BYTES  (SCAN_SMEM_FLOATS * 4)

__device__ __forceinline__ float sigm(float x) { return 1.0f / (1.0f + expf(-x)); }

__global__ void __launch_bounds__(256, 1)
lstm_scan_kernel(const float* __restrict__ xWf, const float* __restrict__ xWb,
                 const float* __restrict__ WhhF, const float* __restrict__ WhhB,
                 float* __restrict__ lout)
{
    extern __shared__ float smem[];
    float* hs  = smem;            // [256][128]
    float* ws  = hs  + 32768;     // [16][256]
    float* gst = ws  + 4096;      // [16][128]
    float* xst = gst + 2048;      // [16][128]
    float* cst = xst + 2048;      // [4][128]
    float* pst = cst + 512;       // [128][16]

    const int tid   = threadIdx.x;
    const int dir   = blockIdx.x >> 6;
    const int slice = blockIdx.x & 63;
    const int j0    = slice << 2;

    const float* xW  = dir ? xWb  : xWf;
    const float* Whh = dir ? WhhB : WhhF;

    {
        const int l  = tid >> 4;
        const int ks = (tid & 15) * 16;
        const int grow = ((l >> 2) * HH) + j0 + (l & 3);
#pragma unroll
        for (int i = 0; i < 16; i += 4)
            *(float4*)&ws[l*256 + ks + i] = *(const float4*)&Whh[(size_t)grow*HH + ks + i];
    }
    {
        float4* d4 = (float4*)hs;
        float4 z = make_float4(0,0,0,0);
#pragma unroll
        for (int i = 0; i < 32; i++) d4[tid + (i << 8)] = z;
        if (tid < 128) { cst[tid] = 0.f; cst[128+tid] = 0.f; cst[256+tid] = 0.f; cst[384+tid] = 0.f; }
    }
    __syncthreads();

    for (int tt = 0; tt < SSQ; tt++) {
        const int t = dir ? (SSQ - 1 - tt) : tt;

        if (tt > 0) {
            const float4* s4 = (const float4*)(g_h[(tt - 1) & 1][dir]);
            float4* d4 = (float4*)hs;
#pragma unroll
            for (int i = 0; i < 32; i++) d4[tid + (i << 8)] = s4[tid + (i << 8)];
        }
#pragma unroll
        for (int half = 0; half < 2; half++) {
            const int p = tid + (half << 8);
            const int q = p >> 7;
            const int b = p & 127;
            float4 v = *(const float4*)&xW[((size_t)b * SSQ + t) * FH + (q << 8) + j0];
            xst[((q<<2)+0)*128 + b] = v.x;
            xst[((q<<2)+1)*128 + b] = v.y;
            xst[((q<<2)+2)*128 + b] = v.z;
            xst[((q<<2)+3)*128 + b] = v.w;
        }
        __syncthreads();

        {
            const int kh = tid >> 7;
            const int ts = tid & 127;
            const int rq = ts >> 5;
            const int bq = ts & 31;
            const int r0 = rq << 2;

            // acc2[i][p]: packed pair of batch columns (bq*4 + 2p, +2p+1)
            uint64_t acc2[4][2];
#pragma unroll
            for (int i = 0; i < 4; i++) { acc2[i][0] = 0ull; acc2[i][1] = 0ull; }

            const float4* hs4 = (const float4*)hs;
            const float4* ws4 = (const float4*)ws;
            const int kw = kh << 5;

#pragma unroll 4
            for (int k4 = 0; k4 < 32; k4++) {
                float w_[4][4];
#pragma unroll
                for (int i = 0; i < 4; i++) {
                    float4 tw = ws4[(r0+i)*64 + kw + k4];
                    w_[i][0]=tw.x; w_[i][1]=tw.y; w_[i][2]=tw.z; w_[i][3]=tw.w;
                }
                const int kb = (kh << 7) + (k4 << 2);
#pragma unroll
                for (int c = 0; c < 4; c++) {
                    float4 hh = hs4[(kb + c)*32 + bq];
                    const uint64_t hp0 = pk2(hh.x, hh.y);
                    const uint64_t hp1 = pk2(hh.z, hh.w);
#pragma unroll
                    for (int i = 0; i < 4; i++) {
                        const uint64_t wp = pk2(w_[i][c], w_[i][c]);
                        fma2(acc2[i][0], wp, hp0);
                        fma2(acc2[i][1], wp, hp1);
                    }
                }
            }
            if (kh) {
#pragma unroll
                for (int i = 0; i < 4; i++) {
                    float v0,v1,v2,v3;
                    upk2(v0, v1, acc2[i][0]);
                    upk2(v2, v3, acc2[i][1]);
                    pst[ts*16 + i*4 + 0] = v0;
                    pst[ts*16 + i*4 + 1] = v1;
                    pst[ts*16 + i*4 + 2] = v2;
                    pst[ts*16 + i*4 + 3] = v3;
                }
            }
            __syncthreads();
            if (!kh) {
#pragma unroll
                for (int i = 0; i < 4; i++) {
                    float v0,v1,v2,v3;
                    upk2(v0, v1, acc2[i][0]);
                    upk2(v2, v3, acc2[i][1]);
                    gst[(r0+i)*128 + (bq<<2) + 0] = v0 + pst[ts*16 + i*4 + 0];
                    gst[(r0+i)*128 + (bq<<2) + 1] = v1 + pst[ts*16 + i*4 + 1];
                    gst[(r0+i)*128 + (bq<<2) + 2] = v2 + pst[ts*16 + i*4 + 2];
                    gst[(r0+i)*128 + (bq<<2) + 3] = v3 + pst[ts*16 + i*4 + 3];
                }
            }
            __syncthreads();
        }

        if (tid < 128) {
            const int b = tid;
            float* hdst = g_h[tt & 1][dir];
            float hj[4];
#pragma unroll
            for (int jj = 0; jj < 4; jj++) {
                float gi = gst[(0  + jj)*128 + b] + xst[(0  + jj)*128 + b];
                float gf = gst[(4  + jj)*128 + b] + xst[(4  + jj)*128 + b];
                float gg = gst[(8  + jj)*128 + b] + xst[(8  + jj)*128 + b];
                float go = gst[(12 + jj)*128 + b] + xst[(12 + jj)*128 + b];
                float c  = cst[jj*128 + b];
                float si = sigm(gi), sf = sigm(gf), so = sigm(go);
                c = sf * c + si * tanhf(gg);
                float h = so * tanhf(c);
                cst[jj*128 + b] = c;
                hdst[(j0 + jj)*128 + b] = h;
                hj[jj] = h;
            }
            *(float4*)&lout[((size_t)b * SSQ + t) * (2*HH) + dir*HH + j0] =
                make_float4(hj[0], hj[1], hj[2], hj[3]);
        }
        __threadfence();
        __syncthreads();

        if (tt < SSQ - 1) {
            if (tid == 0) {
                unsigned gen = *(volatile unsigned*)&g_gen[dir];
                if (atomicAdd(&g_cnt[dir], 1u) == 63u) {
                    atomicExch(&g_cnt[dir], 0u);
                    __threadfence();
                    atomicAdd(&g_gen[dir], 1u);
                } else {
                    while (*(volatile unsigned*)&g_gen[dir] == gen) __nanosleep(32);
                }
                __threadfence();
            }
            __syncthreads();
        }
    }
}

// ---------------- FC (T=9) ----------------
__global__ void __launch_bounds__(256)
fc_kernel(const float* __restrict__ l1, const float* __restrict__ fcw,
          const float* __restrict__ fcb, float* __restrict__ em)
{
    __shared__ float wsm[TT * 512];
    __shared__ float wb[TT];
    const int tid = threadIdx.x;
    for (int i = tid; i < TT*512; i += 256) wsm[i] = fcw[i];
    if (tid < TT) wb[tid] = fcb[tid];
    __syncthreads();

    const int warp = tid >> 5, lane = tid & 31;
    const int m = blockIdx.x * 8 + warp;
    const float* arow = l1 + (size_t)m * 512;
    float a[16];
#pragma unroll
    for (int c = 0; c < 16; c++) a[c] = arow[c*32 + lane];
    float* emrow = em + (size_t)m * TT;
#pragma unroll
    for (int j = 0; j < TT; j++) {
        float s = 0.f;
#pragma unroll
        for (int c = 0; c < 16; c++) s += a[c] * wsm[j*512 + c*32 + lane];
#pragma unroll
        for (int o = 16; o; o >>= 1) s += __shfl_xor_sync(0xffffffffu, s, o);
        if (lane == 0) emrow[j] = s + wb[j];
    }
}

// ---------------- CRF ----------------
__global__ void __launch_bounds__(1024)
crf_kernel(const int* __restrict__ x, const int* __restrict__ tags,
           const float* __restrict__ em, const float* __restrict__ start,
           const float* __restrict__ endv, const float* __restrict__ trans,
           float* __restrict__ partial)
{
    const int gw = (blockIdx.x * blockDim.x + threadIdx.x) >> 5;
    const int lane = threadIdx.x & 31;
    if (gw >= BB) return;
    const int b = gw;
    const float* emr = em + (size_t)b * SSQ * TT;
    const int* tg = tags + (size_t)b * SSQ;
    const int* xb = x + (size_t)b * SSQ;

    float nsum = 0.f; int mcount = 0;
    for (int s = lane; s < SSQ; s += 32) {
        const int m = (xb[s] != 0);
        mcount += m;
        if (s >= 1 && m) {
            const int tp = tg[s-1], tc = tg[s];
            nsum += trans[tp*TT + tc] + emr[(size_t)s*TT + tc];
        }
    }
#pragma unroll
    for (int o = 16; o; o >>= 1) {
        nsum   += __shfl_xor_sync(0xffffffffu, nsum, o);
        mcount += __shfl_xor_sync(0xffffffffu, mcount, o);
    }
    int last = mcount - 1; if (last < 0) last = 0;
    const int t0 = tg[0], tl = tg[last];
    const float num = nsum + start[t0] + emr[t0] + endv[tl];

    float tcol[TT];
#pragma unroll
    for (int i = 0; i < TT; i++) tcol[i] = 0.f;
    float alpha = -1e30f;
    if (lane < TT) {
#pragma unroll
        for (int i = 0; i < TT; i++) tcol[i] = trans[i*TT + lane];
        alpha = start[lane] + emr[lane];
    }
    for (int s = 1; s < SSQ; s++) {
        const float e = (lane < TT) ? emr[(size_t)s*TT + lane] : 0.f;
        const int m = (xb[s] != 0);
        float av[TT];
        float mx = -1e30f;
#pragma unroll
        for (int i = 0; i < TT; i++) {
            const float ai = __shfl_sync(0xffffffffu, alpha, i);
            av[i] = ai + tcol[i];
            mx = fmaxf(mx, av[i]);
        }
        float ssum = 0.f;
#pragma unroll
        for (int i = 0; i < TT; i++) ssum += expf(av[i] - mx);
        const float nxt = e + mx + logf(ssum);
        if (lane < TT && m) alpha = nxt;
    }
    float v = (lane < TT) ? alpha + endv[lane] : -1e30f;
    float mx = v;
#pragma unroll
    for (int o = 16; o; o >>= 1) mx = fmaxf(mx, __shfl_xor_sync(0xffffffffu, mx, o));
    float ex = (lane < TT) ? expf(v - mx) : 0.f;
#pragma unroll
    for (int o = 16; o; o >>= 1) ex += __shfl_xor_sync(0xffffffffu, ex, o);
    const float denom = mx + logf(ex);
    if (lane == 0) partial[b] = denom - num;
}

__global__ void reduce_mean_kernel(const float* __restrict__ partial, float* __restrict__ out)
{
    __shared__ float sm[BB];
    const int t = threadIdx.x;
    sm[t] = partial[t];
    __syncthreads();
    for (int o = 64; o; o >>= 1) { if (t < o) sm[t] += sm[t + o]; __syncthreads(); }
    if (t == 0) out[0] = sm[0] / (float)BB;
}

// ---------------- launch ----------------
extern "C" void kernel_launch(void* const* d_in, const int* in_sizes, int n_in,
                              void* d_out, int out_size)
{
    const int*   x     = (const int*)d_in[0];
    const int*   tags  = (const int*)d_in[1];
    const float* emb   = (const float*)d_in[2];
    const float* Wih0f = (const float*)d_in[3];
    const float* Whh0f = (const float*)d_in[4];
    const float* b0f   = (const float*)d_in[5];
    const float* Wih0b = (const float*)d_in[6];
    const float* Whh0b = (const float*)d_in[7];
    const float* b0b   = (const float*)d_in[8];
    const float* Wih1f = (const float*)d_in[9];
    const float* Whh1f = (const float*)d_in[10];
    const float* b1f   = (const float*)d_in[11];
    const float* Wih1b = (const float*)d_in[12];
    const float* Whh1b = (const float*)d_in[13];
    const float* b1b   = (const float*)d_in[14];
    const float* fcw   = (const float*)d_in[15];
    const float* fcb   = (const float*)d_in[16];
    const float* crf_s = (const float*)d_in[17];
    const float* crf_e = (const float*)d_in[18];
    const float* crf_t = (const float*)d_in[19];
    float* out = (float*)d_out;

    float *gA, *gB, *l0, *l1, *em, *part;
    cudaGetSymbolAddress((void**)&gA, g_gA);
    cudaGetSymbolAddress((void**)&gB, g_gB);
    cudaGetSymbolAddress((void**)&l0, g_l0);
    cudaGetSymbolAddress((void**)&l1, g_l1);
    cudaGetSymbolAddress((void**)&em, g_em);
    cudaGetSymbolAddress((void**)&part, g_part);

    cudaFuncSetAttribute(lstm_scan_kernel,
                         cudaFuncAttributeMaxDynamicSharedMemorySize, SCAN_SMEM_BYTES);

    dim3 gg(MTOT/128, FH/128);

    sgemm_bias_kernel<<<gg, 256>>>(emb, Wih0f, b0f, gA, MTOT, FH, EE, x, EE);
    sgemm_bias_kernel<<<gg, 256>>>(emb, Wih0b, b0b, gB, MTOT, FH, EE, x, EE);
    lstm_scan_kernel<<<128, 256, SCAN_SMEM_BYTES>>>(gA, gB, Whh0f, Whh0b, l0);
    sgemm_bias_kernel<<<gg, 256>>>(l0, Wih1f, b1f, gA, MTOT, FH, 2*HH, nullptr, 2*HH);
    sgemm_bias_kernel<<<gg, 256>>>(l0, Wih1b, b1b, gB, MTOT, FH, 2*HH, nullptr, 2*HH);
    lstm_scan_kernel<<<128, 256, SCAN_SMEM_BYTES>>>(gA, gB, Whh1f, Whh1b, l1);
    fc_kernel<<<MTOT/8, 256>>>(l1, fcw, fcb, em);
    crf_kernel<<<4, 1024>>>(x, tags, em, crf_s, crf_e, crf_t, part);
    reduce_mean_kernel<<<1, 128>>>(part, out);
}